// round 1
// baseline (speedup 1.0000x reference)
#include <cuda_runtime.h>
#include <math.h>

// ---------------------------------------------------------------------------
// Problem constants
//   N=8, Cp=2048, H=W=64 (HW=4096), Cq=256, L=128, NH=8, KD=128, VD=256,
//   BOT=256, FFN=2048.  KV length = L + HW = 4224.
// ---------------------------------------------------------------------------

#define NBATCH 8
#define HWTOT  4096
#define MTOT   4224          // L + HW
#define NPART  6             // attention m-splits
#define MCHUNK 64
#define CHUNKS_PER_PART 11   // 6*11*64 = 4224

// ---------------- scratch (device globals; no runtime allocation) ----------
__device__ float g_pspace[(size_t)NBATCH * 256 * HWTOT];   // pixel_space
__device__ float g_pkv   [(size_t)NBATCH * 384 * HWTOT];   // pixel k|v
__device__ float g_qspace[(size_t)NBATCH * 256 * 128];
__device__ float g_qqkv  [(size_t)NBATCH * 512 * 128];
__device__ float g_ret   [(size_t)NBATCH * 256 * 128];
__device__ float g_qf    [(size_t)NBATCH * 256 * 128];
__device__ float g_ffn   [(size_t)NBATCH * 2048 * 128];
__device__ float g_pacc  [(size_t)64 * NPART * 32 * 128];  // partial attn acc
__device__ float g_pmx   [(size_t)64 * NPART * 128];
__device__ float g_psum  [(size_t)64 * NPART * 128];

__device__ __forceinline__ float gelu_f(float x) {
    // exact gelu: x * 0.5 * (1 + erf(x / sqrt(2)))  (matches approximate=False)
    return 0.5f * x * (1.0f + erff(x * 0.70710678118654752440f));
}

// ---------------------------------------------------------------------------
// Tiled fp32 GEMM:  C[b] = epi( A[M,K] @ B[b][K,N] )
//   EPI 0: bn              -> C = acc*s[m] + bias[m]
//   EPI 1: bn + gelu
//   EPI 2: bn + residual + gelu  (C = gelu(res + acc*s + bias))
//   GELUB : apply gelu() elementwise to B while loading (fuses gelu(pixel)).
// Tile: 128x128, BK=16, 256 threads, 8x8 per-thread micro tile.
// Requires: M%128==0, N%128==0, K%16==0 (true for all call sites here).
// ---------------------------------------------------------------------------
template<int EPI, bool GELUB>
__global__ __launch_bounds__(256, 2) void gemm_k(
    const float* __restrict__ A, const float* __restrict__ B,
    const float* __restrict__ scale, const float* __restrict__ bias,
    const float* __restrict__ res, float* __restrict__ C,
    int M, int N, int K)
{
    const int b  = blockIdx.z;
    const float* Bb = B + (size_t)b * K * N;
    float*       Cb = C + (size_t)b * M * N;
    const int m0 = blockIdx.y * 128;
    const int n0 = blockIdx.x * 128;
    const int tid = threadIdx.x;
    const int tx = tid & 15;
    const int ty = tid >> 4;

    __shared__ float As[16][128];
    __shared__ float Bs[16][128];

    float acc[8][8];
#pragma unroll
    for (int i = 0; i < 8; i++)
#pragma unroll
        for (int j = 0; j < 8; j++) acc[i][j] = 0.0f;

    // A tile load map: thread -> (row, k-quad)
    const int am = tid >> 1;
    const int ak = (tid & 1) * 8;
    // B tile load map: thread -> (k-row, 4-col group); two rows 8 apart
    const int bk = tid >> 5;
    const int bn = (tid & 31) * 4;

    for (int k0 = 0; k0 < K; k0 += 16) {
        const float* ap = A + (size_t)(m0 + am) * K + (k0 + ak);
        float4 a0 = *(const float4*)(ap);
        float4 a1 = *(const float4*)(ap + 4);
        As[ak + 0][am] = a0.x; As[ak + 1][am] = a0.y;
        As[ak + 2][am] = a0.z; As[ak + 3][am] = a0.w;
        As[ak + 4][am] = a1.x; As[ak + 5][am] = a1.y;
        As[ak + 6][am] = a1.z; As[ak + 7][am] = a1.w;

        const float* bp = Bb + (size_t)(k0 + bk) * N + (n0 + bn);
        float4 b0 = *(const float4*)(bp);
        float4 b1 = *(const float4*)(bp + (size_t)8 * N);
        if (GELUB) {
            b0.x = gelu_f(b0.x); b0.y = gelu_f(b0.y);
            b0.z = gelu_f(b0.z); b0.w = gelu_f(b0.w);
            b1.x = gelu_f(b1.x); b1.y = gelu_f(b1.y);
            b1.z = gelu_f(b1.z); b1.w = gelu_f(b1.w);
        }
        *(float4*)&Bs[bk][bn]     = b0;
        *(float4*)&Bs[bk + 8][bn] = b1;
        __syncthreads();

#pragma unroll
        for (int kk = 0; kk < 16; kk++) {
            float ra[8], rb[8];
            *(float4*)&ra[0] = *(const float4*)&As[kk][ty * 8];
            *(float4*)&ra[4] = *(const float4*)&As[kk][ty * 8 + 4];
            *(float4*)&rb[0] = *(const float4*)&Bs[kk][tx * 8];
            *(float4*)&rb[4] = *(const float4*)&Bs[kk][tx * 8 + 4];
#pragma unroll
            for (int i = 0; i < 8; i++)
#pragma unroll
                for (int j = 0; j < 8; j++)
                    acc[i][j] += ra[i] * rb[j];
        }
        __syncthreads();
    }

#pragma unroll
    for (int i = 0; i < 8; i++) {
        const int m = m0 + ty * 8 + i;
        const float s  = scale[m];
        const float bi = bias[m];
#pragma unroll
        for (int j = 0; j < 8; j += 4) {
            const int n = n0 + tx * 8 + j;
            const size_t off = (size_t)m * N + n;
            float4 v;
            v.x = acc[i][j + 0] * s + bi;
            v.y = acc[i][j + 1] * s + bi;
            v.z = acc[i][j + 2] * s + bi;
            v.w = acc[i][j + 3] * s + bi;
            if (EPI == 2) {
                const float4 r = *(const float4*)(res + (size_t)b * M * N + off);
                v.x += r.x; v.y += r.y; v.z += r.z; v.w += r.w;
            }
            if (EPI >= 1) {
                v.x = gelu_f(v.x); v.y = gelu_f(v.y);
                v.z = gelu_f(v.z); v.w = gelu_f(v.w);
            }
            *(float4*)(Cb + off) = v;
        }
    }
}

// ---------------------------------------------------------------------------
// Attention, split-m flash style.
//   q  = qqkv[b][0:128]      (head h rows h*16..h*16+15), scaled by s_sim[h]
//   k  = [ qqkv[b][128:256] | pkv[b][0:128]   ]   (len 128 + 4096)
//   v  = [ qqkv[b][256:512] | pkv[b][128:384] ]
// b_sim is constant along the softmax axis -> cancels; dropped.
// grid (NPART, NH, N); 256 threads: tid&127 = l, tid>>7 selects d-half.
// ---------------------------------------------------------------------------
__global__ __launch_bounds__(256) void attn_partial(
    const float* __restrict__ qqkv, const float* __restrict__ pkv,
    const float* __restrict__ s_sim,
    float* __restrict__ pacc, float* __restrict__ pmx, float* __restrict__ psum)
{
    const int part = blockIdx.x, h = blockIdx.y, b = blockIdx.z;
    const int tid = threadIdx.x;
    const int l = tid & 127;
    const int half = tid >> 7;

    __shared__ float Ks[16][MCHUNK];
    __shared__ float Vs[32][MCHUNK];

    const float ssim = s_sim[h];
    float qr[16];
    const float* qb = qqkv + ((size_t)b * 512 + h * 16) * 128;
#pragma unroll
    for (int d = 0; d < 16; d++) qr[d] = qb[d * 128 + l] * ssim;

    float acc[16];
#pragma unroll
    for (int d = 0; d < 16; d++) acc[d] = 0.0f;
    float mx = -INFINITY, sum = 0.0f;

    const int kd = tid >> 4;            // Ks: 16 rows x 16 float4
    const int kc = (tid & 15) * 4;

    for (int c = 0; c < CHUNKS_PER_PART; c++) {
        const int m0 = part * (MCHUNK * CHUNKS_PER_PART) + c * MCHUNK;
        if (m0 < 128) {
            const float* kb = qqkv + ((size_t)b * 512 + 128 + h * 16) * 128 + m0;
            *(float4*)&Ks[kd][kc] = *(const float4*)(kb + (size_t)kd * 128 + kc);
            const float* vb = qqkv + ((size_t)b * 512 + 256 + h * 32) * 128 + m0;
#pragma unroll
            for (int i = 0; i < 2; i++) {
                const int idx = tid + i * 256;
                const int d = idx >> 4, cc = (idx & 15) * 4;
                *(float4*)&Vs[d][cc] = *(const float4*)(vb + (size_t)d * 128 + cc);
            }
        } else {
            const int s0 = m0 - 128;
            const float* kb = pkv + ((size_t)b * 384 + h * 16) * HWTOT + s0;
            *(float4*)&Ks[kd][kc] = *(const float4*)(kb + (size_t)kd * HWTOT + kc);
            const float* vb = pkv + ((size_t)b * 384 + 128 + h * 32) * HWTOT + s0;
#pragma unroll
            for (int i = 0; i < 2; i++) {
                const int idx = tid + i * 256;
                const int d = idx >> 4, cc = (idx & 15) * 4;
                *(float4*)&Vs[d][cc] = *(const float4*)(vb + (size_t)d * HWTOT + cc);
            }
        }
        __syncthreads();

#pragma unroll 4
        for (int mm = 0; mm < MCHUNK; mm++) {
            float s = 0.0f;
#pragma unroll
            for (int d = 0; d < 16; d++) s += qr[d] * Ks[d][mm];
            if (s > mx) {
                const float corr = expf(mx - s);   // mx = -inf on first hit -> 0
                mx = s;
                sum *= corr;
#pragma unroll
                for (int d = 0; d < 16; d++) acc[d] *= corr;
            }
            const float p = expf(s - mx);
            sum += p;
#pragma unroll
            for (int d = 0; d < 16; d++) acc[d] += p * Vs[half * 16 + d][mm];
        }
        __syncthreads();
    }

    const size_t bh = (size_t)b * 8 + h;
    if (half == 0) {
        pmx [(bh * NPART + part) * 128 + l] = mx;
        psum[(bh * NPART + part) * 128 + l] = sum;
    }
    float* pa = pacc + ((bh * NPART + part) * 32 + half * 16) * 128 + l;
#pragma unroll
    for (int d = 0; d < 16; d++) pa[(size_t)d * 128] = acc[d];
}

// Combine partials, apply bn(s_ret,b_ret) + gelu, write ret (N,VD,L).
__global__ __launch_bounds__(128) void attn_combine(
    const float* __restrict__ pacc, const float* __restrict__ pmx,
    const float* __restrict__ psum,
    const float* __restrict__ s_ret, const float* __restrict__ b_ret,
    float* __restrict__ ret)
{
    const int h = blockIdx.x, b = blockIdx.y;
    const int l = threadIdx.x;
    const size_t bh = (size_t)b * 8 + h;

    float m_[NPART], s_[NPART];
    float mx = -INFINITY;
#pragma unroll
    for (int p = 0; p < NPART; p++) {
        m_[p] = pmx [(bh * NPART + p) * 128 + l];
        s_[p] = psum[(bh * NPART + p) * 128 + l];
        mx = fmaxf(mx, m_[p]);
    }
    float w[NPART];
    float S = 0.0f;
#pragma unroll
    for (int p = 0; p < NPART; p++) { w[p] = expf(m_[p] - mx); S += s_[p] * w[p]; }
    const float inv = 1.0f / S;

#pragma unroll
    for (int d = 0; d < 32; d++) {
        float r = 0.0f;
#pragma unroll
        for (int p = 0; p < NPART; p++)
            r += pacc[((bh * NPART + p) * 32 + d) * 128 + l] * w[p];
        r *= inv;
        const int row = h * 32 + d;
        ret[((size_t)b * 256 + row) * 128 + l] = gelu_f(r * s_ret[row] + b_ret[row]);
    }
}

// ---------------------------------------------------------------------------
extern "C" void kernel_launch(void* const* d_in, const int* in_sizes, int n_in,
                              void* d_out, int out_size)
{
    (void)in_sizes; (void)n_in; (void)out_size;
    const float* pixel = (const float*)d_in[0];
    const float* qfeat = (const float*)d_in[1];
    const float* w_q1  = (const float*)d_in[2];
    const float* s_q1  = (const float*)d_in[3];
    const float* b_q1  = (const float*)d_in[4];
    const float* w_p1  = (const float*)d_in[5];
    const float* s_p1  = (const float*)d_in[6];
    const float* b_p1  = (const float*)d_in[7];
    const float* w_qkv = (const float*)d_in[8];
    const float* s_qkv = (const float*)d_in[9];
    const float* b_qkv = (const float*)d_in[10];
    const float* w_pkv = (const float*)d_in[11];
    const float* s_pkv = (const float*)d_in[12];
    const float* b_pkv = (const float*)d_in[13];
    const float* s_sim = (const float*)d_in[14];
    /* d_in[15] = b_sim: constant along softmax axis, cancels exactly */
    const float* s_ret = (const float*)d_in[16];
    const float* b_ret = (const float*)d_in[17];
    const float* w_c3  = (const float*)d_in[18];
    const float* s_c3  = (const float*)d_in[19];
    const float* b_c3  = (const float*)d_in[20];
    const float* w_f1  = (const float*)d_in[21];
    const float* s_f1  = (const float*)d_in[22];
    const float* b_f1  = (const float*)d_in[23];
    const float* w_f2  = (const float*)d_in[24];
    const float* s_f2  = (const float*)d_in[25];
    const float* b_f2  = (const float*)d_in[26];

    float *pspace, *pkv, *qspace, *qqkv, *retb, *qf, *ffn, *pacc, *pmx, *psum;
    cudaGetSymbolAddress((void**)&pspace, g_pspace);
    cudaGetSymbolAddress((void**)&pkv,    g_pkv);
    cudaGetSymbolAddress((void**)&qspace, g_qspace);
    cudaGetSymbolAddress((void**)&qqkv,   g_qqkv);
    cudaGetSymbolAddress((void**)&retb,   g_ret);
    cudaGetSymbolAddress((void**)&qf,     g_qf);
    cudaGetSymbolAddress((void**)&ffn,    g_ffn);
    cudaGetSymbolAddress((void**)&pacc,   g_pacc);
    cudaGetSymbolAddress((void**)&pmx,    g_pmx);
    cudaGetSymbolAddress((void**)&psum,   g_psum);

    // 1. pixel_space = gelu(bn(w_p1 @ gelu(pixel)))        (N,256,4096)
    gemm_k<1, true ><<<dim3(32, 2, NBATCH), 256>>>(w_p1, pixel, s_p1, b_p1,
                                                   nullptr, pspace, 256, HWTOT, 2048);
    // 2. pixel_kv = bn(w_pkv @ pixel_space)                (N,384,4096)
    gemm_k<0, false><<<dim3(32, 3, NBATCH), 256>>>(w_pkv, pspace, s_pkv, b_pkv,
                                                   nullptr, pkv, 384, HWTOT, 256);
    // 3. query_space = gelu(bn(w_q1 @ query_feature))      (N,256,128)
    gemm_k<1, false><<<dim3(1, 2, NBATCH), 256>>>(w_q1, qfeat, s_q1, b_q1,
                                                  nullptr, qspace, 256, 128, 256);
    // 4. query_qkv = bn(w_qkv @ query_space)               (N,512,128)
    gemm_k<0, false><<<dim3(1, 4, NBATCH), 256>>>(w_qkv, qspace, s_qkv, b_qkv,
                                                  nullptr, qqkv, 512, 128, 256);
    // 5/6. attention -> ret = gelu(bn(attn@v))             (N,256,128)
    attn_partial<<<dim3(NPART, 8, NBATCH), 256>>>(qqkv, pkv, s_sim, pacc, pmx, psum);
    attn_combine<<<dim3(8, NBATCH), 128>>>(pacc, pmx, psum, s_ret, b_ret, retb);
    // 7. qf = gelu(query_feature + bn(w_c3 @ ret))         (N,256,128)
    gemm_k<2, false><<<dim3(1, 2, NBATCH), 256>>>(w_c3, retb, s_c3, b_c3,
                                                  qfeat, qf, 256, 128, 256);
    // 8. ffn = gelu(bn(w_f1 @ qf))                         (N,2048,128)
    gemm_k<1, false><<<dim3(1, 16, NBATCH), 256>>>(w_f1, qf, s_f1, b_f1,
                                                   nullptr, ffn, 2048, 128, 256);
    // 9. out = gelu(qf + bn(w_f2 @ ffn))                   (N,256,128)
    gemm_k<2, false><<<dim3(1, 2, NBATCH), 256>>>(w_f2, ffn, s_f2, b_f2,
                                                  qf, (float*)d_out, 256, 128, 2048);
}

// round 6
// speedup vs baseline: 1.6712x; 1.6712x over previous
#include <cuda_runtime.h>
#include <cuda_bf16.h>
#include <math.h>
#include <stdint.h>

// ---------------------------------------------------------------------------
// Problem constants
//   N=8, Cp=2048, H=W=64 (HW=4096), Cq=256, L=128, NH=8, KD=128, VD=256,
//   BOT=256, FFN=2048.  KV length = L + HW = 4224.
// ---------------------------------------------------------------------------

#define NBATCH 8
#define HWTOT  4096
#define NPART  6
#define MCHUNK 64
#define CHUNKS_PER_PART 11   // 6*11*64 = 4224

// ---------------- scratch (device globals; no runtime allocation) ----------
__device__ float g_pspace[(size_t)NBATCH * 256 * HWTOT];
__device__ float g_pkv   [(size_t)NBATCH * 384 * HWTOT];
__device__ float g_qspace[(size_t)NBATCH * 256 * 128];
__device__ float g_qqkv  [(size_t)NBATCH * 512 * 128];
__device__ float g_ret   [(size_t)NBATCH * 256 * 128];
__device__ float g_qf    [(size_t)NBATCH * 256 * 128];
__device__ float g_ffn   [(size_t)NBATCH * 2048 * 128];
__device__ float g_pacc  [(size_t)64 * NPART * 32 * 128];
__device__ float g_pmx   [(size_t)64 * NPART * 128];
__device__ float g_psum  [(size_t)64 * NPART * 128];

// bf16 hi/lo split operands for tensor-core GEMMs (all K-major)
__device__ __nv_bfloat16 g_xt_h [(size_t)NBATCH * HWTOT * 2048];
__device__ __nv_bfloat16 g_xt_l [(size_t)NBATCH * HWTOT * 2048];
__device__ __nv_bfloat16 g_pst_h[(size_t)NBATCH * HWTOT * 256];
__device__ __nv_bfloat16 g_pst_l[(size_t)NBATCH * HWTOT * 256];
__device__ __nv_bfloat16 g_qft_h[(size_t)NBATCH * 128 * 256];
__device__ __nv_bfloat16 g_qft_l[(size_t)NBATCH * 128 * 256];
__device__ __nv_bfloat16 g_fft_h[(size_t)NBATCH * 128 * 2048];
__device__ __nv_bfloat16 g_fft_l[(size_t)NBATCH * 128 * 2048];
__device__ __nv_bfloat16 g_wp1_h [256 * 2048];
__device__ __nv_bfloat16 g_wp1_l [256 * 2048];
__device__ __nv_bfloat16 g_wpkv_h[384 * 256];
__device__ __nv_bfloat16 g_wpkv_l[384 * 256];
__device__ __nv_bfloat16 g_wf1_h [2048 * 256];
__device__ __nv_bfloat16 g_wf1_l [2048 * 256];
__device__ __nv_bfloat16 g_wf2_h [256 * 2048];
__device__ __nv_bfloat16 g_wf2_l [256 * 2048];

__device__ __forceinline__ float gelu_f(float x) {
    return 0.5f * x * (1.0f + erff(x * 0.70710678118654752440f));
}

// ------------------------- PTX helpers (sm_80-era, safe on sm_100) ---------
__device__ __forceinline__ uint32_t s2u(const void* p) {
    uint32_t a;
    asm("{ .reg .u64 t; cvta.to.shared.u64 t, %1; cvt.u32.u64 %0, t; }"
        : "=r"(a) : "l"(p));
    return a;
}
__device__ __forceinline__ void cpasync16(uint32_t s, const void* g) {
    asm volatile("cp.async.cg.shared.global [%0], [%1], 16;" :: "r"(s), "l"(g));
}
#define CP_COMMIT() asm volatile("cp.async.commit_group;" ::: "memory")
#define CP_WAIT(n)  asm volatile("cp.async.wait_group %0;" :: "n"(n) : "memory")

__device__ __forceinline__ void ldsm4(uint32_t* r, uint32_t a) {
    asm volatile("ldmatrix.sync.aligned.m8n8.x4.shared.b16 {%0,%1,%2,%3}, [%4];"
        : "=r"(r[0]), "=r"(r[1]), "=r"(r[2]), "=r"(r[3]) : "r"(a));
}
__device__ __forceinline__ void ldsm2(uint32_t* r, uint32_t a) {
    asm volatile("ldmatrix.sync.aligned.m8n8.x2.shared.b16 {%0,%1}, [%2];"
        : "=r"(r[0]), "=r"(r[1]) : "r"(a));
}
__device__ __forceinline__ void mma16816(float* d, const uint32_t* a, const uint32_t* b) {
    asm volatile(
        "mma.sync.aligned.m16n8k16.row.col.f32.bf16.bf16.f32 "
        "{%0,%1,%2,%3}, {%4,%5,%6,%7}, {%8,%9}, {%0,%1,%2,%3};"
        : "+f"(d[0]), "+f"(d[1]), "+f"(d[2]), "+f"(d[3])
        : "r"(a[0]), "r"(a[1]), "r"(a[2]), "r"(a[3]), "r"(b[0]), "r"(b[1]));
}

// ---------------------------------------------------------------------------
// hgemm: C[b][Mtot][Ntot] = epi( A[Mtot,K] @ B[b][Ntot,K]^T )
// A,B as bf16 hi/lo splits, K-major rows. Compensation: AhBh + AhBl + AlBh.
// CTA tile 128x128, 8 warps (2m x 4n), warp tile 64x32, BK=32, cp.async
// double buffer, ldmatrix + mma.sync m16n8k16.
// EPI 0: BN; 1: BN+gelu; 2: BN+res+gelu.
// Requires: Mtot%128==0, Ntot%128==0, K%32==0.
// ---------------------------------------------------------------------------
#define HSTRIDE 40                               // bf16 elems per smem row
#define ARRB (128 * HSTRIDE * 2)                 // bytes per operand array
#define STAGEB (4 * ARRB)                        // bytes per stage

template<int EPI>
__global__ __launch_bounds__(256, 1) void hgemm(
    const __nv_bfloat16* __restrict__ Ah, const __nv_bfloat16* __restrict__ Al,
    const __nv_bfloat16* __restrict__ Bh, const __nv_bfloat16* __restrict__ Bl,
    const float* __restrict__ scale, const float* __restrict__ bias,
    const float* __restrict__ res, float* __restrict__ C,
    int Mtot, int Ntot, int K)
{
    extern __shared__ __align__(16) char sm[];
    const int b = blockIdx.z;
    const int m0 = blockIdx.y * 128, n0 = blockIdx.x * 128;
    const int tid = threadIdx.x, wid = tid >> 5, lane = tid & 31;
    const int wm = wid >> 2, wn = wid & 3;

    const int lrow = tid >> 1;             // 0..127
    const int lcv  = (tid & 1) * 2;        // chunk base: 0 or 2 (8 bf16 per chunk)

    // per-thread gmem pointers, pre-offset to (row, chunk)
    const __nv_bfloat16* gp[4];
    gp[0] = Ah + (size_t)(m0 + lrow) * K + lcv * 8;
    gp[1] = Al + (size_t)(m0 + lrow) * K + lcv * 8;
    gp[2] = Bh + ((size_t)b * Ntot + n0 + lrow) * K + lcv * 8;
    gp[3] = Bl + ((size_t)b * Ntot + n0 + lrow) * K + lcv * 8;

    const uint32_t sbase = s2u(sm);
    const uint32_t sdst = sbase + (lrow * HSTRIDE + lcv * 8) * 2;

    float d[4][4][4];
#pragma unroll
    for (int i = 0; i < 4; i++)
#pragma unroll
        for (int j = 0; j < 4; j++)
#pragma unroll
            for (int c = 0; c < 4; c++) d[i][j][c] = 0.0f;

    // per-thread ldmatrix base offsets (elements)
    const int aoff = (wm * 64 + (lane & 15)) * HSTRIDE + (lane >> 4) * 8;
    const int boff = (wn * 32 + (lane & 7)) * HSTRIDE + ((lane >> 3) & 1) * 8;

    const int S = K >> 5;

    // prefetch stage 0
#pragma unroll
    for (int arr = 0; arr < 4; arr++) {
        cpasync16(sdst + arr * ARRB, gp[arr]);
        cpasync16(sdst + arr * ARRB + 16, gp[arr] + 8);
    }
    CP_COMMIT();

    for (int s = 0; s < S; s++) {
        if (s + 1 < S) {
            const int k0 = (s + 1) << 5;
            const uint32_t sb = sdst + ((s + 1) & 1) * STAGEB;
#pragma unroll
            for (int arr = 0; arr < 4; arr++) {
                cpasync16(sb + arr * ARRB, gp[arr] + k0);
                cpasync16(sb + arr * ARRB + 16, gp[arr] + k0 + 8);
            }
            CP_COMMIT();
            CP_WAIT(1);
        } else {
            CP_WAIT(0);
        }
        __syncthreads();

        const uint32_t cb = sbase + (s & 1) * STAGEB;
#pragma unroll
        for (int kk = 0; kk < 32; kk += 16) {
            uint32_t ah[4][4], al[4][4], bh[4][2], bl[4][2];
#pragma unroll
            for (int mi = 0; mi < 4; mi++) {
                const uint32_t ao = cb + (aoff + mi * 16 * HSTRIDE + kk) * 2;
                ldsm4(ah[mi], ao);
                ldsm4(al[mi], ao + ARRB);
            }
#pragma unroll
            for (int ni = 0; ni < 4; ni++) {
                const uint32_t bo = cb + 2 * ARRB + (boff + ni * 8 * HSTRIDE + kk) * 2;
                ldsm2(bh[ni], bo);
                ldsm2(bl[ni], bo + ARRB);
            }
#pragma unroll
            for (int mi = 0; mi < 4; mi++)
#pragma unroll
                for (int ni = 0; ni < 4; ni++) {
                    mma16816(d[mi][ni], ah[mi], bh[ni]);
                    mma16816(d[mi][ni], ah[mi], bl[ni]);
                    mma16816(d[mi][ni], al[mi], bh[ni]);
                }
        }
        __syncthreads();
    }

    // epilogue
#pragma unroll
    for (int mi = 0; mi < 4; mi++) {
        const int r0 = m0 + wm * 64 + mi * 16 + (lane >> 2);
        const int r1 = r0 + 8;
        const float s0 = scale[r0], bb0 = bias[r0];
        const float s1 = scale[r1], bb1 = bias[r1];
        float* c0 = C + ((size_t)b * Mtot + r0) * Ntot + n0;
        float* c1 = C + ((size_t)b * Mtot + r1) * Ntot + n0;
#pragma unroll
        for (int ni = 0; ni < 4; ni++) {
            const int n = wn * 32 + ni * 8 + (lane & 3) * 2;
            float2 v0, v1;
            v0.x = d[mi][ni][0] * s0 + bb0; v0.y = d[mi][ni][1] * s0 + bb0;
            v1.x = d[mi][ni][2] * s1 + bb1; v1.y = d[mi][ni][3] * s1 + bb1;
            if (EPI == 2) {
                const float2 q0 = *(const float2*)(res + ((size_t)b * Mtot + r0) * Ntot + n0 + n);
                const float2 q1 = *(const float2*)(res + ((size_t)b * Mtot + r1) * Ntot + n0 + n);
                v0.x += q0.x; v0.y += q0.y; v1.x += q1.x; v1.y += q1.y;
            }
            if (EPI >= 1) {
                v0.x = gelu_f(v0.x); v0.y = gelu_f(v0.y);
                v1.x = gelu_f(v1.x); v1.y = gelu_f(v1.y);
            }
            *(float2*)(c0 + n) = v0;
            *(float2*)(c1 + n) = v1;
        }
    }
}

// ---------------------------------------------------------------------------
// Prep: transpose (+optional gelu) fp32 [b][C][HW] -> bf16 hi/lo [b][HW][C]
// ---------------------------------------------------------------------------
template<bool G>
__global__ void tsplit_k(const float* __restrict__ src,
                         __nv_bfloat16* __restrict__ hi, __nv_bfloat16* __restrict__ lo,
                         int C, int HW)
{
    __shared__ float t[32][33];
    const int b = blockIdx.z;
    const int c0 = blockIdx.y * 32;
    const int p0 = blockIdx.x * 32;
    const int tx = threadIdx.x, ty = threadIdx.y;

    const float* s = src + ((size_t)b * C + c0) * HW + p0;
#pragma unroll
    for (int j = 0; j < 4; j++) {
        const int ci = ty + j * 8;
        float v = s[(size_t)ci * HW + tx];
        if (G) v = gelu_f(v);
        t[ci][tx] = v;
    }
    __syncthreads();
#pragma unroll
    for (int j = 0; j < 4; j++) {
        const int pi = ty + j * 8;
        const float v = t[tx][pi];
        const __nv_bfloat16 h = __float2bfloat16(v);
        const size_t o = ((size_t)b * HW + p0 + pi) * C + c0 + tx;
        hi[o] = h;
        lo[o] = __float2bfloat16(v - __bfloat162float(h));
    }
}

__global__ void wsplit_k(const float* __restrict__ src,
                         __nv_bfloat16* __restrict__ hi, __nv_bfloat16* __restrict__ lo, int n)
{
    const int i = blockIdx.x * 256 + threadIdx.x;
    if (i < n) {
        const float v = src[i];
        const __nv_bfloat16 h = __float2bfloat16(v);
        hi[i] = h;
        lo[i] = __float2bfloat16(v - __bfloat162float(h));
    }
}

// ---------------------------------------------------------------------------
// Small fp32 GEMM (query-side small projections only)
// ---------------------------------------------------------------------------
template<int EPI, bool GELUB>
__global__ __launch_bounds__(256, 2) void gemm_k(
    const float* __restrict__ A, const float* __restrict__ B,
    const float* __restrict__ scale, const float* __restrict__ bias,
    const float* __restrict__ res, float* __restrict__ C,
    int M, int N, int K)
{
    const int b  = blockIdx.z;
    const float* Bb = B + (size_t)b * K * N;
    float*       Cb = C + (size_t)b * M * N;
    const int m0 = blockIdx.y * 128;
    const int n0 = blockIdx.x * 128;
    const int tid = threadIdx.x;
    const int tx = tid & 15;
    const int ty = tid >> 4;

    __shared__ float As[16][128];
    __shared__ float Bs[16][128];

    float acc[8][8];
#pragma unroll
    for (int i = 0; i < 8; i++)
#pragma unroll
        for (int j = 0; j < 8; j++) acc[i][j] = 0.0f;

    const int am = tid >> 1;
    const int ak = (tid & 1) * 8;
    const int bk = tid >> 5;
    const int bn = (tid & 31) * 4;

    for (int k0 = 0; k0 < K; k0 += 16) {
        const float* ap = A + (size_t)(m0 + am) * K + (k0 + ak);
        float4 a0 = *(const float4*)(ap);
        float4 a1 = *(const float4*)(ap + 4);
        As[ak + 0][am] = a0.x; As[ak + 1][am] = a0.y;
        As[ak + 2][am] = a0.z; As[ak + 3][am] = a0.w;
        As[ak + 4][am] = a1.x; As[ak + 5][am] = a1.y;
        As[ak + 6][am] = a1.z; As[ak + 7][am] = a1.w;

        const float* bp = Bb + (size_t)(k0 + bk) * N + (n0 + bn);
        float4 b0 = *(const float4*)(bp);
        float4 b1 = *(const float4*)(bp + (size_t)8 * N);
        if (GELUB) {
            b0.x = gelu_f(b0.x); b0.y = gelu_f(b0.y);
            b0.z = gelu_f(b0.z); b0.w = gelu_f(b0.w);
            b1.x = gelu_f(b1.x); b1.y = gelu_f(b1.y);
            b1.z = gelu_f(b1.z); b1.w = gelu_f(b1.w);
        }
        *(float4*)&Bs[bk][bn]     = b0;
        *(float4*)&Bs[bk + 8][bn] = b1;
        __syncthreads();

#pragma unroll
        for (int kk = 0; kk < 16; kk++) {
            float ra[8], rb[8];
            *(float4*)&ra[0] = *(const float4*)&As[kk][ty * 8];
            *(float4*)&ra[4] = *(const float4*)&As[kk][ty * 8 + 4];
            *(float4*)&rb[0] = *(const float4*)&Bs[kk][tx * 8];
            *(float4*)&rb[4] = *(const float4*)&Bs[kk][tx * 8 + 4];
#pragma unroll
            for (int i = 0; i < 8; i++)
#pragma unroll
                for (int j = 0; j < 8; j++)
                    acc[i][j] += ra[i] * rb[j];
        }
        __syncthreads();
    }

#pragma unroll
    for (int i = 0; i < 8; i++) {
        const int m = m0 + ty * 8 + i;
        const float s  = scale[m];
        const float bi = bias[m];
#pragma unroll
        for (int j = 0; j < 8; j += 4) {
            const int n = n0 + tx * 8 + j;
            const size_t off = (size_t)m * N + n;
            float4 v;
            v.x = acc[i][j + 0] * s + bi;
            v.y = acc[i][j + 1] * s + bi;
            v.z = acc[i][j + 2] * s + bi;
            v.w = acc[i][j + 3] * s + bi;
            if (EPI == 2) {
                const float4 r = *(const float4*)(res + (size_t)b * M * N + off);
                v.x += r.x; v.y += r.y; v.z += r.z; v.w += r.w;
            }
            if (EPI >= 1) {
                v.x = gelu_f(v.x); v.y = gelu_f(v.y);
                v.z = gelu_f(v.z); v.w = gelu_f(v.w);
            }
            *(float4*)(Cb + off) = v;
        }
    }
}

// ---------------------------------------------------------------------------
// Attention, split-m flash style (fp32). b_sim cancels in softmax; dropped.
// ---------------------------------------------------------------------------
__global__ __launch_bounds__(256) void attn_partial(
    const float* __restrict__ qqkv, const float* __restrict__ pkv,
    const float* __restrict__ s_sim,
    float* __restrict__ pacc, float* __restrict__ pmx, float* __restrict__ psum)
{
    const int part = blockIdx.x, h = blockIdx.y, b = blockIdx.z;
    const int tid = threadIdx.x;
    const int l = tid & 127;
    const int half = tid >> 7;

    __shared__ float Ks[16][MCHUNK];
    __shared__ float Vs[32][MCHUNK];

    const float ssim = s_sim[h];
    float qr[16];
    const float* qb = qqkv + ((size_t)b * 512 + h * 16) * 128;
#pragma unroll
    for (int d = 0; d < 16; d++) qr[d] = qb[d * 128 + l] * ssim;

    float acc[16];
#pragma unroll
    for (int d = 0; d < 16; d++) acc[d] = 0.0f;
    float mx = -INFINITY, sum = 0.0f;

    const int kd = tid >> 4;
    const int kc = (tid & 15) * 4;

    for (int c = 0; c < CHUNKS_PER_PART; c++) {
        const int m0 = part * (MCHUNK * CHUNKS_PER_PART) + c * MCHUNK;
        if (m0 < 128) {
            const float* kb = qqkv + ((size_t)b * 512 + 128 + h * 16) * 128 + m0;
            *(float4*)&Ks[kd][kc] = *(const float4*)(kb + (size_t)kd * 128 + kc);
            const float* vb = qqkv + ((size_t)b * 512 + 256 + h * 32) * 128 + m0;
#pragma unroll
            for (int i = 0; i < 2; i++) {
                const int idx = tid + i * 256;
                const int d = idx >> 4, cc = (idx & 15) * 4;
                *(float4*)&Vs[d][cc] = *(const float4*)(vb + (size_t)d * 128 + cc);
            }
        } else {
            const int s0 = m0 - 128;
            const float* kb = pkv + ((size_t)b * 384 + h * 16) * HWTOT + s0;
            *(float4*)&Ks[kd][kc] = *(const float4*)(kb + (size_t)kd * HWTOT + kc);
            const float* vb = pkv + ((size_t)b * 384 + 128 + h * 32) * HWTOT + s0;
#pragma unroll
            for (int i = 0; i < 2; i++) {
                const int idx = tid + i * 256;
                const int d = idx >> 4, cc = (idx & 15) * 4;
                *(float4*)&Vs[d][cc] = *(const float4*)(vb + (size_t)d * HWTOT + cc);
            }
        }
        __syncthreads();

#pragma unroll
        for (int g = 0; g < 4; g++) {
            float sv[16];
            float gm = -INFINITY;
#pragma unroll
            for (int j = 0; j < 16; j++) {
                const int mm = g * 16 + j;
                float s = 0.0f;
#pragma unroll
                for (int d = 0; d < 16; d++) s += qr[d] * Ks[d][mm];
                sv[j] = s;
                gm = fmaxf(gm, s);
            }
            if (gm > mx) {
                const float corr = __expf(mx - gm);
                mx = gm;
                sum *= corr;
#pragma unroll
                for (int d = 0; d < 16; d++) acc[d] *= corr;
            }
#pragma unroll
            for (int j = 0; j < 16; j++) {
                const float p = __expf(sv[j] - mx);
                sum += p;
#pragma unroll
                for (int d = 0; d < 16; d++) acc[d] += p * Vs[half * 16 + d][g * 16 + j];
            }
        }
        __syncthreads();
    }

    const size_t bh = (size_t)b * 8 + h;
    if (half == 0) {
        pmx [(bh * NPART + part) * 128 + l] = mx;
        psum[(bh * NPART + part) * 128 + l] = sum;
    }
    float* pa = pacc + ((bh * NPART + part) * 32 + half * 16) * 128 + l;
#pragma unroll
    for (int d = 0; d < 16; d++) pa[(size_t)d * 128] = acc[d];
}

__global__ __launch_bounds__(128) void attn_combine(
    const float* __restrict__ pacc, const float* __restrict__ pmx,
    const float* __restrict__ psum,
    const float* __restrict__ s_ret, const float* __restrict__ b_ret,
    float* __restrict__ ret)
{
    const int h = blockIdx.x, b = blockIdx.y;
    const int l = threadIdx.x;
    const size_t bh = (size_t)b * 8 + h;

    float m_[NPART], s_[NPART];
    float mx = -INFINITY;
#pragma unroll
    for (int p = 0; p < NPART; p++) {
        m_[p] = pmx [(bh * NPART + p) * 128 + l];
        s_[p] = psum[(bh * NPART + p) * 128 + l];
        mx = fmaxf(mx, m_[p]);
    }
    float w[NPART];
    float S = 0.0f;
#pragma unroll
    for (int p = 0; p < NPART; p++) { w[p] = __expf(m_[p] - mx); S += s_[p] * w[p]; }
    const float inv = 1.0f / S;

#pragma unroll
    for (int d = 0; d < 32; d++) {
        float r = 0.0f;
#pragma unroll
        for (int p = 0; p < NPART; p++)
            r += pacc[((bh * NPART + p) * 32 + d) * 128 + l] * w[p];
        r *= inv;
        const int row = h * 32 + d;
        ret[((size_t)b * 256 + row) * 128 + l] = gelu_f(r * s_ret[row] + b_ret[row]);
    }
}

// ---------------------------------------------------------------------------
extern "C" void kernel_launch(void* const* d_in, const int* in_sizes, int n_in,
                              void* d_out, int out_size)
{
    (void)in_sizes; (void)n_in; (void)out_size;
    const float* pixel = (const float*)d_in[0];
    const float* qfeat = (const float*)d_in[1];
    const float* w_q1  = (const float*)d_in[2];
    const float* s_q1  = (const float*)d_in[3];
    const float* b_q1  = (const float*)d_in[4];
    const float* w_p1  = (const float*)d_in[5];
    const float* s_p1  = (const float*)d_in[6];
    const float* b_p1  = (const float*)d_in[7];
    const float* w_qkv = (const float*)d_in[8];
    const float* s_qkv = (const float*)d_in[9];
    const float* b_qkv = (const float*)d_in[10];
    const float* w_pkv = (const float*)d_in[11];
    const float* s_pkv = (const float*)d_in[12];
    const float* b_pkv = (const float*)d_in[13];
    const float* s_sim = (const float*)d_in[14];
    /* d_in[15] = b_sim: constant along softmax axis, cancels exactly */
    const float* s_ret = (const float*)d_in[16];
    const float* b_ret = (const float*)d_in[17];
    const float* w_c3  = (const float*)d_in[18];
    const float* s_c3  = (const float*)d_in[19];
    const float* b_c3  = (const float*)d_in[20];
    const float* w_f1  = (const float*)d_in[21];
    const float* s_f1  = (const float*)d_in[22];
    const float* b_f1  = (const float*)d_in[23];
    const float* w_f2  = (const float*)d_in[24];
    const float* s_f2  = (const float*)d_in[25];
    const float* b_f2  = (const float*)d_in[26];

    float *pspace, *pkv, *qspace, *qqkv, *retb, *qf, *ffn, *pacc, *pmx, *psum;
    __nv_bfloat16 *xth, *xtl, *psth, *pstl, *qfth, *qftl, *ffth, *fftl;
    __nv_bfloat16 *wp1h, *wp1l, *wpkvh, *wpkvl, *wf1h, *wf1l, *wf2h, *wf2l;
    cudaGetSymbolAddress((void**)&pspace, g_pspace);
    cudaGetSymbolAddress((void**)&pkv,    g_pkv);
    cudaGetSymbolAddress((void**)&qspace, g_qspace);
    cudaGetSymbolAddress((void**)&qqkv,   g_qqkv);
    cudaGetSymbolAddress((void**)&retb,   g_ret);
    cudaGetSymbolAddress((void**)&qf,     g_qf);
    cudaGetSymbolAddress((void**)&ffn,    g_ffn);
    cudaGetSymbolAddress((void**)&pacc,   g_pacc);
    cudaGetSymbolAddress((void**)&pmx,    g_pmx);
    cudaGetSymbolAddress((void**)&psum,   g_psum);
    cudaGetSymbolAddress((void**)&xth,    g_xt_h);
    cudaGetSymbolAddress((void**)&xtl,    g_xt_l);
    cudaGetSymbolAddress((void**)&psth,   g_pst_h);
    cudaGetSymbolAddress((void**)&pstl,   g_pst_l);
    cudaGetSymbolAddress((void**)&qfth,   g_qft_h);
    cudaGetSymbolAddress((void**)&qftl,   g_qft_l);
    cudaGetSymbolAddress((void**)&ffth,   g_fft_h);
    cudaGetSymbolAddress((void**)&fftl,   g_fft_l);
    cudaGetSymbolAddress((void**)&wp1h,   g_wp1_h);
    cudaGetSymbolAddress((void**)&wp1l,   g_wp1_l);
    cudaGetSymbolAddress((void**)&wpkvh,  g_wpkv_h);
    cudaGetSymbolAddress((void**)&wpkvl,  g_wpkv_l);
    cudaGetSymbolAddress((void**)&wf1h,   g_wf1_h);
    cudaGetSymbolAddress((void**)&wf1l,   g_wf1_l);
    cudaGetSymbolAddress((void**)&wf2h,   g_wf2_h);
    cudaGetSymbolAddress((void**)&wf2l,   g_wf2_l);

    const int HS = 2 * STAGEB;   // 81920 bytes dynamic smem
    cudaFuncSetAttribute(hgemm<0>, cudaFuncAttributeMaxDynamicSharedMemorySize, HS);
    cudaFuncSetAttribute(hgemm<1>, cudaFuncAttributeMaxDynamicSharedMemorySize, HS);
    cudaFuncSetAttribute(hgemm<2>, cudaFuncAttributeMaxDynamicSharedMemorySize, HS);

    // 0. weight splits (independent)
    wsplit_k<<<(256 * 2048 + 255) / 256, 256>>>(w_p1, wp1h, wp1l, 256 * 2048);
    wsplit_k<<<(384 * 256 + 255) / 256, 256>>>(w_pkv, wpkvh, wpkvl, 384 * 256);
    wsplit_k<<<(2048 * 256 + 255) / 256, 256>>>(w_f1, wf1h, wf1l, 2048 * 256);
    wsplit_k<<<(256 * 2048 + 255) / 256, 256>>>(w_f2, wf2h, wf2l, 256 * 2048);

    // 1. pixel_space = gelu(bn(w_p1 @ gelu(pixel)))        (N,256,4096)
    tsplit_k<true><<<dim3(HWTOT / 32, 2048 / 32, NBATCH), dim3(32, 8)>>>(
        pixel, xth, xtl, 2048, HWTOT);
    hgemm<1><<<dim3(32, 2, NBATCH), 256, HS>>>(
        wp1h, wp1l, xth, xtl, s_p1, b_p1, nullptr, pspace, 256, HWTOT, 2048);

    // 2. pixel_kv = bn(w_pkv @ pixel_space)                (N,384,4096)
    tsplit_k<false><<<dim3(HWTOT / 32, 256 / 32, NBATCH), dim3(32, 8)>>>(
        pspace, psth, pstl, 256, HWTOT);
    hgemm<0><<<dim3(32, 3, NBATCH), 256, HS>>>(
        wpkvh, wpkvl, psth, pstl, s_pkv, b_pkv, nullptr, pkv, 384, HWTOT, 256);

    // 3. query_space = gelu(bn(w_q1 @ query_feature))      (N,256,128)
    gemm_k<1, false><<<dim3(1, 2, NBATCH), 256>>>(w_q1, qfeat, s_q1, b_q1,
                                                  nullptr, qspace, 256, 128, 256);
    // 4. query_qkv = bn(w_qkv @ query_space)               (N,512,128)
    gemm_k<0, false><<<dim3(1, 4, NBATCH), 256>>>(w_qkv, qspace, s_qkv, b_qkv,
                                                  nullptr, qqkv, 512, 128, 256);
    // 5/6. attention -> ret = gelu(bn(attn@v))             (N,256,128)
    attn_partial<<<dim3(NPART, 8, NBATCH), 256>>>(qqkv, pkv, s_sim, pacc, pmx, psum);
    attn_combine<<<dim3(8, NBATCH), 128>>>(pacc, pmx, psum, s_ret, b_ret, retb);
    // 7. qf = gelu(query_feature + bn(w_c3 @ ret))         (N,256,128)
    gemm_k<2, false><<<dim3(1, 2, NBATCH), 256>>>(w_c3, retb, s_c3, b_c3,
                                                  qfeat, qf, 256, 128, 256);
    // 8. ffn = gelu(bn(w_f1 @ qf))                         (N,2048,128)
    tsplit_k<false><<<dim3(128 / 32, 256 / 32, NBATCH), dim3(32, 8)>>>(
        qf, qfth, qftl, 256, 128);
    hgemm<1><<<dim3(1, 16, NBATCH), 256, HS>>>(
        wf1h, wf1l, qfth, qftl, s_f1, b_f1, nullptr, ffn, 2048, 128, 256);
    // 9. out = gelu(qf + bn(w_f2 @ ffn))                   (N,256,128)
    tsplit_k<false><<<dim3(128 / 32, 2048 / 32, NBATCH), dim3(32, 8)>>>(
        ffn, ffth, fftl, 2048, 128);
    hgemm<2><<<dim3(1, 2, NBATCH), 256, HS>>>(
        wf2h, wf2l, ffth, fftl, s_f2, b_f2, qf, (float*)d_out, 256, 128, 2048);
}